// round 1
// baseline (speedup 1.0000x reference)
#include <cuda_runtime.h>
#include <cstdint>

#define B_      32
#define N_      500
#define D_      2048
#define K_      128
#define SIGMA   0.05f
#define THREADS 256
#define EPT     8          // D_/THREADS elements per thread

// monotone float -> uint mapping (bigger float -> bigger uint)
__device__ __forceinline__ unsigned int f2u(float f) {
    unsigned int u = __float_as_uint(f);
    // negative: flip all bits; non-negative: set sign bit
    return u ^ (((unsigned int)((int)u >> 31)) | 0x80000000u);
}

// exclusive block scan over 256 threads (returns exclusive prefix of v)
__device__ __forceinline__ unsigned int block_excl_scan(unsigned int v,
                                                        unsigned int* warpSums) {
    const int lane = threadIdx.x & 31;
    const int wid  = threadIdx.x >> 5;
    unsigned int x = v;
    #pragma unroll
    for (int o = 1; o < 32; o <<= 1) {
        unsigned int y = __shfl_up_sync(0xffffffffu, x, o);
        if (lane >= o) x += y;
    }
    if (lane == 31) warpSums[wid] = x;
    __syncthreads();
    if (wid == 0 && lane < 8) {
        unsigned int s = warpSums[lane];
        #pragma unroll
        for (int o = 1; o < 8; o <<= 1) {
            unsigned int y = __shfl_up_sync(0xffu, s, o);
            if (lane >= o) s += y;
        }
        warpSums[lane] = s;
    }
    __syncthreads();
    unsigned int base = (wid > 0) ? warpSums[wid - 1] : 0u;
    return base + x - v;   // exclusive
}

__global__ void zero_kernel(float* __restrict__ p, int n) {
    int i = blockIdx.x * blockDim.x + threadIdx.x;
    int stride = gridDim.x * blockDim.x;
    for (; i < n; i += stride) p[i] = 0.0f;
}

__global__ __launch_bounds__(THREADS)
void perturbed_topk_kernel(const float* __restrict__ x,
                           const float* __restrict__ noise,
                           float* __restrict__ ind,    // (B,K,D) or null
                           float* __restrict__ idxf)   // (B,N,K) or null
{
    __shared__ unsigned int keys[D_];
    __shared__ unsigned int hist[256];
    __shared__ unsigned int warpSums[8];
    __shared__ unsigned int sh_sel;
    __shared__ unsigned int sh_krem;

    const int t = threadIdx.x;
    const int b = blockIdx.x / N_;

    // ---- load + perturb: perturbed = x + SIGMA*noise, store orderable keys ----
    const float4* xv = (const float4*)(x + (size_t)b * D_);
    const float4* nv = (const float4*)(noise + (size_t)blockIdx.x * D_);
    #pragma unroll
    for (int i = 0; i < 2; i++) {
        int vi = t + i * THREADS;                 // float4 index 0..511
        float4 xx = xv[vi];
        float4 nn = nv[vi];
        keys[vi * 4 + 0] = f2u(fmaf(SIGMA, nn.x, xx.x));
        keys[vi * 4 + 1] = f2u(fmaf(SIGMA, nn.y, xx.y));
        keys[vi * 4 + 2] = f2u(fmaf(SIGMA, nn.z, xx.z));
        keys[vi * 4 + 3] = f2u(fmaf(SIGMA, nn.w, xx.w));
    }
    __syncthreads();

    // ---- 4-pass radix select: find threshold key T s.t.
    //      count(key > T) < K <= count(key >= T) ----
    unsigned int prefHigh = 0;
    unsigned int maskHigh = 0;
    unsigned int krem = K_;

    #pragma unroll
    for (int pass = 0; pass < 4; pass++) {
        const int shift = 24 - pass * 8;
        hist[t] = 0;
        __syncthreads();
        #pragma unroll
        for (int i = 0; i < EPT; i++) {
            unsigned int k = keys[t * EPT + i];
            if ((k & maskHigh) == prefHigh)
                atomicAdd(&hist[(k >> shift) & 0xFFu], 1u);
        }
        __syncthreads();
        // inclusive suffix scan over hist (Hillis-Steele)
        #pragma unroll
        for (int off = 1; off < 256; off <<= 1) {
            unsigned int v   = hist[t];
            unsigned int add = (t + off < 256) ? hist[t + off] : 0u;
            __syncthreads();
            hist[t] = v + add;
            __syncthreads();
        }
        unsigned int st  = hist[t];
        unsigned int nxt = (t < 255) ? hist[t + 1] : 0u;
        if (st >= krem && nxt < krem) {          // exactly one thread matches
            sh_sel  = (unsigned int)t;
            sh_krem = krem - nxt;
        }
        __syncthreads();
        prefHigh |= (sh_sel << shift);
        maskHigh |= (0xFFu << shift);
        krem = sh_krem;
        __syncthreads();
    }

    const unsigned int T = prefHigh;   // exact K-th key
    const unsigned int R = krem;       // how many keys == T to take (lowest indices first)

    // ---- count per-chunk, scan, compact in index order ----
    unsigned int cnt_eq = 0, cnt_gt = 0;
    #pragma unroll
    for (int i = 0; i < EPT; i++) {
        unsigned int k = keys[t * EPT + i];
        cnt_gt += (k > T);
        cnt_eq += (k == T);
    }
    unsigned int eqBefore = block_excl_scan(cnt_eq, warpSums);
    int takeEq = (int)cnt_eq;
    int room   = (int)R - (int)eqBefore;
    if (room < 0) room = 0;
    if (takeEq > room) takeEq = room;
    unsigned int selLocal = cnt_gt + (unsigned int)takeEq;
    __syncthreads();
    unsigned int outBase = block_excl_scan(selLocal, warpSums);

    unsigned int j = outBase;
    unsigned int eqRank = eqBefore;
    const size_t idxBase = (size_t)blockIdx.x * K_;
    const float inv_n = 1.0f / (float)N_;

    #pragma unroll
    for (int i = 0; i < EPT; i++) {
        int e = t * EPT + i;
        unsigned int k = keys[e];
        bool isEq = (k == T);
        bool sel  = (k > T) || (isEq && (eqRank < R));
        eqRank += isEq ? 1u : 0u;
        if (sel) {
            if (idxf) idxf[idxBase + j] = (float)e;
            if (ind)  atomicAdd(&ind[((size_t)b * K_ + j) * D_ + e], inv_n);
            j++;
        }
    }
}

extern "C" void kernel_launch(void* const* d_in, const int* in_sizes, int n_in,
                              void* d_out, int out_size) {
    // inputs: x (32*2048 = 65536), noise (32*500*2048 = 32768000)
    const float* x     = (const float*)d_in[0];
    const float* noise = (const float*)d_in[1];
    if (n_in >= 2 && in_sizes[0] != B_ * D_) {   // defensive: order by size
        x     = (const float*)d_in[1];
        noise = (const float*)d_in[0];
    }

    const long long IND = (long long)B_ * K_ * D_;   // 8388608
    const long long IDX = (long long)B_ * N_ * K_;   // 2048000

    float* ind  = nullptr;
    float* idxf = nullptr;
    if ((long long)out_size >= IND + IDX) {
        ind  = (float*)d_out;
        idxf = (float*)d_out + IND;
    } else if ((long long)out_size == IND) {
        ind = (float*)d_out;
    } else if ((long long)out_size == IDX) {
        idxf = (float*)d_out;
    } else {
        ind = (float*)d_out;   // best-effort fallback
    }

    if (ind) zero_kernel<<<1024, 256>>>(ind, (int)IND);
    perturbed_topk_kernel<<<B_ * N_, THREADS>>>(x, noise, ind, idxf);
}